// round 2
// baseline (speedup 1.0000x reference)
#include <cuda_runtime.h>
#include <math.h>

#define BB   2
#define TT   2048
#define DD   1024
#define HH   16
#define DH   64
#define HD   1024      // H*DH
#define NREL 7

// ---------------- scratch (no allocation allowed) ----------------
__device__ float g_q[BB*HH*TT*DH];      // [b][h][t][d]
__device__ float g_k[BB*HH*TT*DH];
__device__ float g_v[BB*HH*TT*DH];
__device__ float g_attn[BB*TT*HD];      // [b][t][h*DH+d]
__device__ float g_small[BB*HH*TT*NREL];
__device__ float g_pk[NREL*HD];         // [r][h*DH+d]

// =================================================================
// SGEMM: C[4096,1024] = A[4096,1024] @ B[1024,1024] + bias
// mode 0: write out[((b*H+h)*T + t)*DH + d]   (BHTD layout)
// mode 1: write out[r*1024 + c]               (plain row-major)
// 128x128 block tile, BK=8, 256 threads, 8x8 per thread.
// =================================================================
__global__ void __launch_bounds__(256)
sgemm_kernel(const float* __restrict__ A, const float* __restrict__ B,
             const float* __restrict__ bias, float* __restrict__ out, int mode)
{
    const int N = 1024, K = 1024;
    __shared__ float As[8][128];
    __shared__ float Bs[8][128];

    int tid = threadIdx.x;
    int tx = tid & 15, ty = tid >> 4;
    int rowBase = blockIdx.y * 128;
    int colBase = blockIdx.x * 128;

    float acc[8][8];
#pragma unroll
    for (int i = 0; i < 8; i++)
#pragma unroll
        for (int j = 0; j < 8; j++) acc[i][j] = 0.f;

    int aRow = tid >> 1;           // 0..127
    int aCol = (tid & 1) * 4;      // 0 or 4
    int bRow = tid >> 5;           // 0..7
    int bCol = (tid & 31) * 4;     // 0..124

    const float* Aptr = A + (size_t)(rowBase + aRow) * K + aCol;
    const float* Bptr = B + (size_t)bRow * N + colBase + bCol;

    for (int k0 = 0; k0 < K; k0 += 8) {
        float4 a4 = *(const float4*)(Aptr + k0);
        float4 b4 = *(const float4*)(Bptr + (size_t)k0 * N);
        As[aCol + 0][aRow] = a4.x;
        As[aCol + 1][aRow] = a4.y;
        As[aCol + 2][aRow] = a4.z;
        As[aCol + 3][aRow] = a4.w;
        *(float4*)&Bs[bRow][bCol] = b4;
        __syncthreads();
#pragma unroll
        for (int kk = 0; kk < 8; kk++) {
            float a[8], b[8];
            *(float4*)&a[0] = *(const float4*)&As[kk][ty * 4];
            *(float4*)&a[4] = *(const float4*)&As[kk][64 + ty * 4];
            *(float4*)&b[0] = *(const float4*)&Bs[kk][tx * 4];
            *(float4*)&b[4] = *(const float4*)&Bs[kk][64 + tx * 4];
#pragma unroll
            for (int i = 0; i < 8; i++)
#pragma unroll
                for (int j = 0; j < 8; j++)
                    acc[i][j] = fmaf(a[i], b[j], acc[i][j]);
        }
        __syncthreads();
    }

#pragma unroll
    for (int ih = 0; ih < 2; ih++)
#pragma unroll
        for (int i = 0; i < 4; i++) {
            int r = rowBase + ih * 64 + ty * 4 + i;
#pragma unroll
            for (int jh = 0; jh < 2; jh++) {
                int c = colBase + jh * 64 + tx * 4;
                float4 bv = *(const float4*)(bias + c);
                float4 v;
                v.x = acc[ih * 4 + i][jh * 4 + 0] + bv.x;
                v.y = acc[ih * 4 + i][jh * 4 + 1] + bv.y;
                v.z = acc[ih * 4 + i][jh * 4 + 2] + bv.z;
                v.w = acc[ih * 4 + i][jh * 4 + 3] + bv.w;
                if (mode == 0) {
                    int b_ = r >> 11, t = r & 2047, h = c >> 6, d = c & 63;
                    *(float4*)(out + (((size_t)(b_ * HH + h) * TT + t) << 6) + d) = v;
                } else {
                    *(float4*)(out + (size_t)r * 1024 + c) = v;
                }
            }
        }
}

// =================================================================
// pk[r][n] = sum_k pos_emb[r][k] * Wk[k][n] + bk[n]    (7 x 1024)
// =================================================================
__global__ void __launch_bounds__(256)
pk_kernel(const float* __restrict__ pe, const float* __restrict__ Wk,
          const float* __restrict__ bk, float* __restrict__ pk)
{
    int r = blockIdx.x;            // 0..6
    int n0 = threadIdx.x * 4;      // 0..1020
    float4 acc = make_float4(0.f, 0.f, 0.f, 0.f);
    const float* per = pe + (size_t)r * 1024;
    for (int k = 0; k < 1024; k++) {
        float a = per[k];
        float4 w = *(const float4*)(Wk + (size_t)k * 1024 + n0);
        acc.x = fmaf(a, w.x, acc.x);
        acc.y = fmaf(a, w.y, acc.y);
        acc.z = fmaf(a, w.z, acc.z);
        acc.w = fmaf(a, w.w, acc.w);
    }
    float4 b = *(const float4*)(bk + n0);
    acc.x += b.x; acc.y += b.y; acc.z += b.z; acc.w += b.w;
    *(float4*)(pk + (size_t)r * 1024 + n0) = acc;
}

// =================================================================
// small[b,h,t,r] = sum_d (q[b,h,t,d] + rel_bias[h,d]) * pk[r,h,d]
// One warp per (b,h,t).
// =================================================================
__global__ void __launch_bounds__(256)
small_kernel(const float* __restrict__ q, const float* __restrict__ relb,
             const float* __restrict__ pk, float* __restrict__ out)
{
    int warp = (blockIdx.x * blockDim.x + threadIdx.x) >> 5;  // (b*H+h)*T + t
    int lane = threadIdx.x & 31;
    if (warp >= BB * HH * TT) return;
    int bh = warp >> 11;
    int h = bh & 15;
    const float* qrow = q + (size_t)warp * DH;
    float q0 = qrow[lane]      + relb[h * DH + lane];
    float q1 = qrow[lane + 32] + relb[h * DH + lane + 32];
#pragma unroll
    for (int r = 0; r < NREL; r++) {
        const float* pkr = pk + (size_t)r * HD + h * DH;
        float p = q0 * pkr[lane] + q1 * pkr[lane + 32];
#pragma unroll
        for (int s = 16; s >= 1; s >>= 1)
            p += __shfl_xor_sync(0xffffffffu, p, s);
        if (lane == 0) out[(size_t)warp * NREL + r] = p;
    }
}

// =================================================================
// Flash attention with relative bias lookup.
// Grid: (T/64, B*H).  256 threads (16x16), 4x4 micro-tiles.
// smem operands d-major so both GEMM operands are LDS.128-friendly.
// =================================================================
#define AT_STRIDE 68
#define ATTN_SMEM_FLOATS (4 * 64 * AT_STRIDE + 64 * 8)
#define ATTN_SMEM_BYTES  (ATTN_SMEM_FLOATS * 4)

__global__ void __launch_bounds__(256)
attn_kernel(const float* __restrict__ gq, const float* __restrict__ gk,
            const float* __restrict__ gv, const float* __restrict__ gsmall,
            const float* __restrict__ ub, float* __restrict__ gout)
{
    extern __shared__ float sm[];
    float* Qt  = sm;                       // [64 d][68]  q+u, d-major
    float* Kt  = sm + 64 * AT_STRIDE;      // [64 d][68]  k, d-major
    float* Vs  = sm + 2 * 64 * AT_STRIDE;  // [64 key][68] v, natural
    float* Pt  = sm + 3 * 64 * AT_STRIDE;  // [64 key][68] p, key-major
    float* ssm = sm + 4 * 64 * AT_STRIDE;  // [64][8] relative logits

    int tid = threadIdx.x;
    int tx = tid & 15, ty = tid >> 4;
    int bh = blockIdx.y;                   // b*H + h
    int h = bh & 15;
    int qbase = blockIdx.x * 64;

    const size_t head_off = (size_t)bh * TT * DH;
    const float* qg = gq + head_off + (size_t)qbase * DH;
    const float* kg = gk + head_off;
    const float* vg = gv + head_off;

    // load Q tile (+content bias), transposed to d-major
    {
        int r = tid >> 2;
        int d0 = (tid & 3) * 16;
#pragma unroll
        for (int x = 0; x < 4; x++) {
            float4 v  = *(const float4*)(qg + (size_t)r * DH + d0 + x * 4);
            float4 u4 = *(const float4*)(ub + h * DH + d0 + x * 4);
            Qt[(d0 + x * 4 + 0) * AT_STRIDE + r] = v.x + u4.x;
            Qt[(d0 + x * 4 + 1) * AT_STRIDE + r] = v.y + u4.y;
            Qt[(d0 + x * 4 + 2) * AT_STRIDE + r] = v.z + u4.z;
            Qt[(d0 + x * 4 + 3) * AT_STRIDE + r] = v.w + u4.w;
        }
    }
    // load the 7 relative logits per query row
    for (int i = tid; i < 64 * NREL; i += 256) {
        int r = i / NREL, j = i - r * NREL;
        ssm[r * 8 + j] = gsmall[((size_t)bh * TT + qbase + r) * NREL + j];
    }

    float m[4], l[4], o[4][4];
#pragma unroll
    for (int i = 0; i < 4; i++) {
        m[i] = -INFINITY; l[i] = 0.f;
#pragma unroll
        for (int j = 0; j < 4; j++) o[i][j] = 0.f;
    }

    const float scale = 0.125f;  // 1/sqrt(64)

    for (int kb = 0; kb < TT; kb += 64) {
        __syncthreads();   // prior iter done with Kt/Vs/Pt; first iter: Qt/ssm visible
        {
            int r = tid >> 2;
            int d0 = (tid & 3) * 16;
            const float* kr = kg + (size_t)(kb + r) * DH + d0;
            const float* vr = vg + (size_t)(kb + r) * DH + d0;
#pragma unroll
            for (int x = 0; x < 4; x++) {
                float4 k4 = *(const float4*)(kr + x * 4);
                Kt[(d0 + x * 4 + 0) * AT_STRIDE + r] = k4.x;
                Kt[(d0 + x * 4 + 1) * AT_STRIDE + r] = k4.y;
                Kt[(d0 + x * 4 + 2) * AT_STRIDE + r] = k4.z;
                Kt[(d0 + x * 4 + 3) * AT_STRIDE + r] = k4.w;
                float4 v4 = *(const float4*)(vr + x * 4);
                *(float4*)&Vs[r * AT_STRIDE + d0 + x * 4] = v4;
            }
        }
        __syncthreads();

        // S = Qu . K^T   (4x4 per thread: rows ty*4+i, cols tx*4+j)
        float s[4][4];
#pragma unroll
        for (int i = 0; i < 4; i++)
#pragma unroll
            for (int j = 0; j < 4; j++) s[i][j] = 0.f;

#pragma unroll 8
        for (int d = 0; d < 64; d++) {
            float a[4], b[4];
            *(float4*)a = *(const float4*)(Qt + d * AT_STRIDE + ty * 4);
            *(float4*)b = *(const float4*)(Kt + d * AT_STRIDE + tx * 4);
#pragma unroll
            for (int i = 0; i < 4; i++)
#pragma unroll
                for (int j = 0; j < 4; j++)
                    s[i][j] = fmaf(a[i], b[j], s[i][j]);
        }

        // rel bias + scale + online softmax (row stats replicated across tx)
#pragma unroll
        for (int i = 0; i < 4; i++) {
            int row = ty * 4 + i;
            int tg = qbase + row;
            float rmax = -INFINITY;
#pragma unroll
            for (int j = 0; j < 4; j++) {
                int Tc = kb + tx * 4 + j;
                int ridx = tg - Tc;
                ridx = (ridx > 3) ? 3 : (ridx < -3 ? -3 : ridx);
                float val = (s[i][j] + ssm[row * 8 + ridx + 3]) * scale;
                s[i][j] = val;
                rmax = fmaxf(rmax, val);
            }
#pragma unroll
            for (int w = 8; w >= 1; w >>= 1)
                rmax = fmaxf(rmax, __shfl_xor_sync(0xffffffffu, rmax, w));
            float mnew = fmaxf(m[i], rmax);
            float f = __expf(m[i] - mnew);
            m[i] = mnew;
            float rsum = 0.f;
#pragma unroll
            for (int j = 0; j < 4; j++) {
                s[i][j] = __expf(s[i][j] - mnew);
                rsum += s[i][j];
            }
#pragma unroll
            for (int w = 8; w >= 1; w >>= 1)
                rsum += __shfl_xor_sync(0xffffffffu, rsum, w);
            l[i] = l[i] * f + rsum;
#pragma unroll
            for (int j = 0; j < 4; j++) o[i][j] *= f;
            // write P transposed (key-major) for the O GEMM
#pragma unroll
            for (int j = 0; j < 4; j++)
                Pt[(tx * 4 + j) * AT_STRIDE + row] = s[i][j];
        }
        __syncthreads();

        // O += P . V   (k-dim = key index c)
#pragma unroll 8
        for (int c = 0; c < 64; c++) {
            float a[4], b[4];
            *(float4*)a = *(const float4*)(Pt + c * AT_STRIDE + ty * 4);
            *(float4*)b = *(const float4*)(Vs + c * AT_STRIDE + tx * 4);
#pragma unroll
            for (int i = 0; i < 4; i++)
#pragma unroll
                for (int j = 0; j < 4; j++)
                    o[i][j] = fmaf(a[i], b[j], o[i][j]);
        }
    }

    // write O/l to [b][t][h*DH+d]
    int b_ = bh >> 4;
#pragma unroll
    for (int i = 0; i < 4; i++) {
        float inv = 1.0f / l[i];
        int t = qbase + ty * 4 + i;
        float4 v;
        v.x = o[i][0] * inv; v.y = o[i][1] * inv;
        v.z = o[i][2] * inv; v.w = o[i][3] * inv;
        *(float4*)(gout + ((size_t)(b_ * TT + t)) * HD + h * DH + tx * 4) = v;
    }
}

// =================================================================
extern "C" void kernel_launch(void* const* d_in, const int* in_sizes, int n_in,
                              void* d_out, int out_size)
{
    const float* query   = (const float*)d_in[0];
    const float* key_in  = (const float*)d_in[1];
    const float* value   = (const float*)d_in[2];
    const float* Wq      = (const float*)d_in[3];
    const float* bq      = (const float*)d_in[4];
    const float* Wk      = (const float*)d_in[5];
    const float* bk      = (const float*)d_in[6];
    const float* Wv      = (const float*)d_in[7];
    const float* bv      = (const float*)d_in[8];
    const float* Wo      = (const float*)d_in[9];
    const float* bo      = (const float*)d_in[10];
    const float* u_bias  = (const float*)d_in[11];  // content_bias
    const float* v_bias  = (const float*)d_in[12];  // relative_bias
    const float* pos_emb = (const float*)d_in[13];

    float *q, *k, *v, *attn, *small, *pk;
    cudaGetSymbolAddress((void**)&q,     g_q);
    cudaGetSymbolAddress((void**)&k,     g_k);
    cudaGetSymbolAddress((void**)&v,     g_v);
    cudaGetSymbolAddress((void**)&attn,  g_attn);
    cudaGetSymbolAddress((void**)&small, g_small);
    cudaGetSymbolAddress((void**)&pk,    g_pk);

    cudaFuncSetAttribute(attn_kernel,
                         cudaFuncAttributeMaxDynamicSharedMemorySize,
                         ATTN_SMEM_BYTES);

    dim3 gg(8, 32);  // N/128, M/128
    sgemm_kernel<<<gg, 256>>>(query,  Wq, bq, q, 0);
    sgemm_kernel<<<gg, 256>>>(key_in, Wk, bk, k, 0);
    sgemm_kernel<<<gg, 256>>>(value,  Wv, bv, v, 0);
    pk_kernel<<<NREL, 256>>>(pos_emb, Wk, bk, pk);

    int nwarps = BB * HH * TT;
    small_kernel<<<(nwarps * 32 + 255) / 256, 256>>>(q, v_bias, pk, small);

    attn_kernel<<<dim3(TT / 64, BB * HH), 256, ATTN_SMEM_BYTES>>>(
        q, k, v, small, u_bias, attn);

    sgemm_kernel<<<gg, 256>>>(attn, Wo, bo, (float*)d_out, 1);
}

// round 3
// speedup vs baseline: 1.0731x; 1.0731x over previous
#include <cuda_runtime.h>
#include <math.h>

#define BB   2
#define TT   2048
#define DD   1024
#define HH   16
#define DH   64
#define HD   1024      // H*DH
#define NREL 7
#define PK_SLICES 16

// ---------------- scratch (no allocation allowed) ----------------
__device__ float g_q[BB*HH*TT*DH];      // [b][h][t][d]
__device__ float g_k[BB*HH*TT*DH];
__device__ float g_v[BB*HH*TT*DH];
__device__ float g_attn[BB*TT*HD];      // [b][t][h*DH+d]
__device__ float g_small[BB*HH*TT*NREL];
__device__ float g_pk[NREL*HD];         // [r][h*DH+d]
__device__ float g_pk_part[PK_SLICES][NREL*HD];

// =================================================================
// SGEMM: C[4096,1024] = A[4096,1024] @ B[1024,1024] + bias
// mode 0: write out[((b*H+h)*T + t)*DH + d]   (BHTD layout)
// mode 1: write out[r*1024 + c]               (plain row-major)
// 128x128 block tile, BK=8, 256 threads, 8x8 per thread.
// Global loads for tile k+1 prefetched into registers during compute of tile k.
// =================================================================
__global__ void __launch_bounds__(256)
sgemm_kernel(const float* __restrict__ A, const float* __restrict__ B,
             const float* __restrict__ bias, float* __restrict__ out, int mode)
{
    const int N = 1024, K = 1024;
    __shared__ float As[8][128];
    __shared__ float Bs[8][128];

    int tid = threadIdx.x;
    int tx = tid & 15, ty = tid >> 4;
    int rowBase = blockIdx.y * 128;
    int colBase = blockIdx.x * 128;

    float acc[8][8];
#pragma unroll
    for (int i = 0; i < 8; i++)
#pragma unroll
        for (int j = 0; j < 8; j++) acc[i][j] = 0.f;

    int aRow = tid >> 1;           // 0..127
    int aCol = (tid & 1) * 4;      // 0 or 4
    int bRow = tid >> 5;           // 0..7
    int bCol = (tid & 31) * 4;     // 0..124

    const float* Aptr = A + (size_t)(rowBase + aRow) * K + aCol;
    const float* Bptr = B + (size_t)bRow * N + colBase + bCol;

    // prologue: load first tile
    float4 a4 = *(const float4*)(Aptr);
    float4 b4 = *(const float4*)(Bptr);

    for (int k0 = 0; k0 < K; k0 += 8) {
        As[aCol + 0][aRow] = a4.x;
        As[aCol + 1][aRow] = a4.y;
        As[aCol + 2][aRow] = a4.z;
        As[aCol + 3][aRow] = a4.w;
        *(float4*)&Bs[bRow][bCol] = b4;
        __syncthreads();

        // prefetch next tile while computing this one
        if (k0 + 8 < K) {
            a4 = *(const float4*)(Aptr + k0 + 8);
            b4 = *(const float4*)(Bptr + (size_t)(k0 + 8) * N);
        }

#pragma unroll
        for (int kk = 0; kk < 8; kk++) {
            float a[8], b[8];
            *(float4*)&a[0] = *(const float4*)&As[kk][ty * 4];
            *(float4*)&a[4] = *(const float4*)&As[kk][64 + ty * 4];
            *(float4*)&b[0] = *(const float4*)&Bs[kk][tx * 4];
            *(float4*)&b[4] = *(const float4*)&Bs[kk][64 + tx * 4];
#pragma unroll
            for (int i = 0; i < 8; i++)
#pragma unroll
                for (int j = 0; j < 8; j++)
                    acc[i][j] = fmaf(a[i], b[j], acc[i][j]);
        }
        __syncthreads();
    }

#pragma unroll
    for (int ih = 0; ih < 2; ih++)
#pragma unroll
        for (int i = 0; i < 4; i++) {
            int r = rowBase + ih * 64 + ty * 4 + i;
#pragma unroll
            for (int jh = 0; jh < 2; jh++) {
                int c = colBase + jh * 64 + tx * 4;
                float4 bv = *(const float4*)(bias + c);
                float4 v;
                v.x = acc[ih * 4 + i][jh * 4 + 0] + bv.x;
                v.y = acc[ih * 4 + i][jh * 4 + 1] + bv.y;
                v.z = acc[ih * 4 + i][jh * 4 + 2] + bv.z;
                v.w = acc[ih * 4 + i][jh * 4 + 3] + bv.w;
                if (mode == 0) {
                    int b_ = r >> 11, t = r & 2047, h = c >> 6, d = c & 63;
                    *(float4*)(out + (((size_t)(b_ * HH + h) * TT + t) << 6) + d) = v;
                } else {
                    *(float4*)(out + (size_t)r * 1024 + c) = v;
                }
            }
        }
}

// =================================================================
// pk split-K: part[s][r][n] = sum_{k in slice s} pe[r][k] * Wk[k][n]
// grid (NREL, PK_SLICES), 256 threads. Then deterministic reduce.
// =================================================================
__global__ void __launch_bounds__(256)
pk_part_kernel(const float* __restrict__ pe, const float* __restrict__ Wk,
               float* __restrict__ part)
{
    int r = blockIdx.x;
    int s = blockIdx.y;
    int n0 = threadIdx.x * 4;
    const int kps = DD / PK_SLICES;   // 64
    float4 acc = make_float4(0.f, 0.f, 0.f, 0.f);
    const float* per = pe + (size_t)r * DD;
    int kend = (s + 1) * kps;
    for (int k = s * kps; k < kend; k++) {
        float a = per[k];
        float4 w = *(const float4*)(Wk + (size_t)k * HD + n0);
        acc.x = fmaf(a, w.x, acc.x);
        acc.y = fmaf(a, w.y, acc.y);
        acc.z = fmaf(a, w.z, acc.z);
        acc.w = fmaf(a, w.w, acc.w);
    }
    *(float4*)(part + ((size_t)s * NREL + r) * HD + n0) = acc;
}

__global__ void __launch_bounds__(256)
pk_reduce_kernel(const float* __restrict__ part, const float* __restrict__ bk,
                 float* __restrict__ pk)
{
    int r = blockIdx.x;
    int n0 = threadIdx.x * 4;
    float4 acc = *(const float4*)(bk + n0);
#pragma unroll
    for (int s = 0; s < PK_SLICES; s++) {
        float4 p = *(const float4*)(part + ((size_t)s * NREL + r) * HD + n0);
        acc.x += p.x; acc.y += p.y; acc.z += p.z; acc.w += p.w;
    }
    *(float4*)(pk + (size_t)r * HD + n0) = acc;
}

// =================================================================
// small[b,h,t,r] = sum_d (q[b,h,t,d] + rel_bias[h,d]) * pk[r,h,d]
// One warp per (b,h,t).
// =================================================================
__global__ void __launch_bounds__(256)
small_kernel(const float* __restrict__ q, const float* __restrict__ relb,
             const float* __restrict__ pk, float* __restrict__ out)
{
    int warp = (blockIdx.x * blockDim.x + threadIdx.x) >> 5;  // (b*H+h)*T + t
    int lane = threadIdx.x & 31;
    if (warp >= BB * HH * TT) return;
    int bh = warp >> 11;
    int h = bh & 15;
    const float* qrow = q + (size_t)warp * DH;
    float q0 = qrow[lane]      + relb[h * DH + lane];
    float q1 = qrow[lane + 32] + relb[h * DH + lane + 32];
#pragma unroll
    for (int r = 0; r < NREL; r++) {
        const float* pkr = pk + (size_t)r * HD + h * DH;
        float p = q0 * pkr[lane] + q1 * pkr[lane + 32];
#pragma unroll
        for (int s = 16; s >= 1; s >>= 1)
            p += __shfl_xor_sync(0xffffffffu, p, s);
        if (lane == 0) out[(size_t)warp * NREL + r] = p;
    }
}

// =================================================================
// Flash attention with relative bias lookup.
// Grid: (T/64, B*H).  256 threads (16x16), 4x4 micro-tiles.
// K/V tiles prefetched into registers one iteration ahead.
// =================================================================
#define AT_STRIDE 68
#define ATTN_SMEM_FLOATS (4 * 64 * AT_STRIDE + 64 * 8)
#define ATTN_SMEM_BYTES  (ATTN_SMEM_FLOATS * 4)

__global__ void __launch_bounds__(256)
attn_kernel(const float* __restrict__ gq, const float* __restrict__ gk,
            const float* __restrict__ gv, const float* __restrict__ gsmall,
            const float* __restrict__ ub, float* __restrict__ gout)
{
    extern __shared__ float sm[];
    float* Qt  = sm;                       // [64 d][68]  q+u, d-major
    float* Kt  = sm + 64 * AT_STRIDE;      // [64 d][68]  k, d-major
    float* Vs  = sm + 2 * 64 * AT_STRIDE;  // [64 key][68] v, natural
    float* Pt  = sm + 3 * 64 * AT_STRIDE;  // [64 key][68] p, key-major
    float* ssm = sm + 4 * 64 * AT_STRIDE;  // [64][8] relative logits

    int tid = threadIdx.x;
    int tx = tid & 15, ty = tid >> 4;
    int bh = blockIdx.y;                   // b*H + h
    int h = bh & 15;
    int qbase = blockIdx.x * 64;

    const size_t head_off = (size_t)bh * TT * DH;
    const float* qg = gq + head_off + (size_t)qbase * DH;
    const float* kg = gk + head_off;
    const float* vg = gv + head_off;

    const int rld = tid >> 2;          // row for loads, 0..63
    const int d0  = (tid & 3) * 16;    // 16-float chunk

    // load Q tile (+content bias), transposed to d-major
    {
#pragma unroll
        for (int x = 0; x < 4; x++) {
            float4 v  = *(const float4*)(qg + (size_t)rld * DH + d0 + x * 4);
            float4 u4 = *(const float4*)(ub + h * DH + d0 + x * 4);
            Qt[(d0 + x * 4 + 0) * AT_STRIDE + rld] = v.x + u4.x;
            Qt[(d0 + x * 4 + 1) * AT_STRIDE + rld] = v.y + u4.y;
            Qt[(d0 + x * 4 + 2) * AT_STRIDE + rld] = v.z + u4.z;
            Qt[(d0 + x * 4 + 3) * AT_STRIDE + rld] = v.w + u4.w;
        }
    }
    // load the 7 relative logits per query row
    for (int i = tid; i < 64 * NREL; i += 256) {
        int r = i / NREL, j = i - r * NREL;
        ssm[r * 8 + j] = gsmall[((size_t)bh * TT + qbase + r) * NREL + j];
    }

    float m[4], l[4], o[4][4];
#pragma unroll
    for (int i = 0; i < 4; i++) {
        m[i] = -INFINITY; l[i] = 0.f;
#pragma unroll
        for (int j = 0; j < 4; j++) o[i][j] = 0.f;
    }

    const float scale = 0.125f;  // 1/sqrt(64)

    // prologue: load first K/V tile into registers
    float4 kreg[4], vreg[4];
    {
        const float* kr = kg + (size_t)rld * DH + d0;
        const float* vr = vg + (size_t)rld * DH + d0;
#pragma unroll
        for (int x = 0; x < 4; x++) {
            kreg[x] = *(const float4*)(kr + x * 4);
            vreg[x] = *(const float4*)(vr + x * 4);
        }
    }

    for (int kb = 0; kb < TT; kb += 64) {
        __syncthreads();   // prior iter done with Kt/Vs/Pt; first iter: Qt/ssm visible
#pragma unroll
        for (int x = 0; x < 4; x++) {
            Kt[(d0 + x * 4 + 0) * AT_STRIDE + rld] = kreg[x].x;
            Kt[(d0 + x * 4 + 1) * AT_STRIDE + rld] = kreg[x].y;
            Kt[(d0 + x * 4 + 2) * AT_STRIDE + rld] = kreg[x].z;
            Kt[(d0 + x * 4 + 3) * AT_STRIDE + rld] = kreg[x].w;
            *(float4*)&Vs[rld * AT_STRIDE + d0 + x * 4] = vreg[x];
        }
        __syncthreads();

        // S = Qu . K^T   (4x4 per thread: rows ty*4+i, cols tx*4+j)
        float s[4][4];
#pragma unroll
        for (int i = 0; i < 4; i++)
#pragma unroll
            for (int j = 0; j < 4; j++) s[i][j] = 0.f;

#pragma unroll 8
        for (int d = 0; d < 64; d++) {
            float a[4], b[4];
            *(float4*)a = *(const float4*)(Qt + d * AT_STRIDE + ty * 4);
            *(float4*)b = *(const float4*)(Kt + d * AT_STRIDE + tx * 4);
#pragma unroll
            for (int i = 0; i < 4; i++)
#pragma unroll
                for (int j = 0; j < 4; j++)
                    s[i][j] = fmaf(a[i], b[j], s[i][j]);
        }

        // prefetch next K/V tile into registers (covered by softmax + O GEMM)
        if (kb + 64 < TT) {
            const float* kr = kg + (size_t)(kb + 64 + rld) * DH + d0;
            const float* vr = vg + (size_t)(kb + 64 + rld) * DH + d0;
#pragma unroll
            for (int x = 0; x < 4; x++) {
                kreg[x] = *(const float4*)(kr + x * 4);
                vreg[x] = *(const float4*)(vr + x * 4);
            }
        }

        // rel bias + scale + online softmax (row stats replicated across tx)
#pragma unroll
        for (int i = 0; i < 4; i++) {
            int row = ty * 4 + i;
            int tg = qbase + row;
            float rmax = -INFINITY;
#pragma unroll
            for (int j = 0; j < 4; j++) {
                int Tc = kb + tx * 4 + j;
                int ridx = tg - Tc;
                ridx = (ridx > 3) ? 3 : (ridx < -3 ? -3 : ridx);
                float val = (s[i][j] + ssm[row * 8 + ridx + 3]) * scale;
                s[i][j] = val;
                rmax = fmaxf(rmax, val);
            }
#pragma unroll
            for (int w = 8; w >= 1; w >>= 1)
                rmax = fmaxf(rmax, __shfl_xor_sync(0xffffffffu, rmax, w));
            float mnew = fmaxf(m[i], rmax);
            float f = __expf(m[i] - mnew);
            m[i] = mnew;
            float rsum = 0.f;
#pragma unroll
            for (int j = 0; j < 4; j++) {
                s[i][j] = __expf(s[i][j] - mnew);
                rsum += s[i][j];
            }
#pragma unroll
            for (int w = 8; w >= 1; w >>= 1)
                rsum += __shfl_xor_sync(0xffffffffu, rsum, w);
            l[i] = l[i] * f + rsum;
#pragma unroll
            for (int j = 0; j < 4; j++) o[i][j] *= f;
            // write P transposed (key-major) for the O GEMM
#pragma unroll
            for (int j = 0; j < 4; j++)
                Pt[(tx * 4 + j) * AT_STRIDE + row] = s[i][j];
        }
        __syncthreads();

        // O += P . V   (k-dim = key index c)
#pragma unroll 8
        for (int c = 0; c < 64; c++) {
            float a[4], b[4];
            *(float4*)a = *(const float4*)(Pt + c * AT_STRIDE + ty * 4);
            *(float4*)b = *(const float4*)(Vs + c * AT_STRIDE + tx * 4);
#pragma unroll
            for (int i = 0; i < 4; i++)
#pragma unroll
                for (int j = 0; j < 4; j++)
                    o[i][j] = fmaf(a[i], b[j], o[i][j]);
        }
    }

    // write O/l to [b][t][h*DH+d]
    int b_ = bh >> 4;
#pragma unroll
    for (int i = 0; i < 4; i++) {
        float inv = 1.0f / l[i];
        int t = qbase + ty * 4 + i;
        float4 v;
        v.x = o[i][0] * inv; v.y = o[i][1] * inv;
        v.z = o[i][2] * inv; v.w = o[i][3] * inv;
        *(float4*)(gout + ((size_t)(b_ * TT + t)) * HD + h * DH + tx * 4) = v;
    }
}

// =================================================================
extern "C" void kernel_launch(void* const* d_in, const int* in_sizes, int n_in,
                              void* d_out, int out_size)
{
    const float* query   = (const float*)d_in[0];
    const float* key_in  = (const float*)d_in[1];
    const float* value   = (const float*)d_in[2];
    const float* Wq      = (const float*)d_in[3];
    const float* bq      = (const float*)d_in[4];
    const float* Wk      = (const float*)d_in[5];
    const float* bk      = (const float*)d_in[6];
    const float* Wv      = (const float*)d_in[7];
    const float* bv      = (const float*)d_in[8];
    const float* Wo      = (const float*)d_in[9];
    const float* bo      = (const float*)d_in[10];
    const float* u_bias  = (const float*)d_in[11];  // content_bias
    const float* v_bias  = (const float*)d_in[12];  // relative_bias
    const float* pos_emb = (const float*)d_in[13];

    float *q, *k, *v, *attn, *small, *pk, *pkp;
    cudaGetSymbolAddress((void**)&q,     g_q);
    cudaGetSymbolAddress((void**)&k,     g_k);
    cudaGetSymbolAddress((void**)&v,     g_v);
    cudaGetSymbolAddress((void**)&attn,  g_attn);
    cudaGetSymbolAddress((void**)&small, g_small);
    cudaGetSymbolAddress((void**)&pk,    g_pk);
    cudaGetSymbolAddress((void**)&pkp,   g_pk_part);

    cudaFuncSetAttribute(attn_kernel,
                         cudaFuncAttributeMaxDynamicSharedMemorySize,
                         ATTN_SMEM_BYTES);

    dim3 gg(8, 32);  // N/128, M/128
    sgemm_kernel<<<gg, 256>>>(query,  Wq, bq, q, 0);
    sgemm_kernel<<<gg, 256>>>(key_in, Wk, bk, k, 0);
    sgemm_kernel<<<gg, 256>>>(value,  Wv, bv, v, 0);

    pk_part_kernel<<<dim3(NREL, PK_SLICES), 256>>>(pos_emb, Wk, pkp);
    pk_reduce_kernel<<<NREL, 256>>>(pkp, bk, pk);

    int nwarps = BB * HH * TT;
    small_kernel<<<(nwarps * 32 + 255) / 256, 256>>>(q, v_bias, pk, small);

    attn_kernel<<<dim3(TT / 64, BB * HH), 256, ATTN_SMEM_BYTES>>>(
        q, k, v, small, u_bias, attn);

    sgemm_kernel<<<gg, 256>>>(attn, Wo, bo, (float*)d_out, 1);
}